// round 12
// baseline (speedup 1.0000x reference)
#include <cuda_runtime.h>
#include <cuda_bf16.h>
#include <cuda_fp16.h>
#include <cstdint>

// Problem constants
#define NPTS   1000000
#define FEAT   32
#define RES_H  512
#define RES_W  128
#define TSTEP  (1.0f/256.0f)   // 1/(2*RES_W), exactly representable
// XLA rewrites (-pts / 1.6f) as (-pts * (1/1.6f)); 1/1.6f rounds to exactly 0.625f.
#define INV_BOUNDS 0.625f

// Transposed fp16 planes: [plane][h][w][f] — 3*512*128*32*2 = 12.6 MB, L2-resident.
__device__ __half g_T16[3 * RES_H * RES_W * FEAT];

// ---------------------------------------------------------------------------
// Kernel 1: transpose+convert each plane [F,H,W] fp32 -> [H,W,F] fp16.
// One block per (plane, h): 1536 blocks x 256 threads.
// ---------------------------------------------------------------------------
__global__ void __launch_bounds__(256)
transpose_planes(const float* __restrict__ p0,
                 const float* __restrict__ p1,
                 const float* __restrict__ p2) {
    __shared__ float tile[32][129];
    int b   = blockIdx.x;
    int h   = b & 511;
    int pl  = b >> 9;
    const float* src = (pl == 0) ? p0 : ((pl == 1) ? p1 : p2);
    int tid = threadIdx.x;

    #pragma unroll
    for (int k = 0; k < 16; k++) {
        int idx = tid + 256 * k;
        int f = idx >> 7;
        int w = idx & 127;
        tile[f][w] = src[f * (RES_H * RES_W) + h * RES_W + w];
    }
    __syncthreads();

    __half2* dst = reinterpret_cast<__half2*>(g_T16) + (size_t)(pl * RES_H + h) * (RES_W * FEAT / 2);
    #pragma unroll
    for (int k = 0; k < 8; k++) {
        int idx2 = tid + 256 * k;
        int w  = idx2 >> 4;
        int fp = idx2 & 15;
        dst[idx2] = __floats2half2_rn(tile[2 * fp][w], tile[2 * fp + 1][w]);
    }
}

// ---------------------------------------------------------------------------
// Index math: IEEE round-to-nearest ops, round-half-even conversion.
// ---------------------------------------------------------------------------
__device__ __forceinline__ int idx_w(float c) {
    float v = __fmul_rn(__fmul_rn(__fadd_rn(c, 1.0f), 0.5f), 127.0f);
    int k = __float2int_rn(v);
    return min(127, max(0, k));
}
__device__ __forceinline__ int idx_h(float c) {
    float v = __fmul_rn(__fmul_rn(__fadd_rn(c, 1.0f), 0.5f), 511.0f);
    int k = __float2int_rn(v);
    return min(511, max(0, k));
}

__device__ __forceinline__ void gather_addrs(float t, float px, float py, float pz,
                                             int sub, unsigned& c0, unsigned& c1, unsigned& c2) {
    int ix  = idx_w(t);
    c0 = (unsigned)(((0 * RES_H + idx_h(px)) * RES_W + ix) * (FEAT / 4)) + sub;
    c1 = (unsigned)(((1 * RES_H + idx_h(py)) * RES_W + ix) * (FEAT / 4)) + sub;
    c2 = (unsigned)(((2 * RES_H + idx_h(pz)) * RES_W + ix) * (FEAT / 4)) + sub;
}

__device__ __forceinline__ float4 prod3(uint2 ua, uint2 ub, uint2 uc) {
    float2 a0 = __half22float2(*reinterpret_cast<__half2*>(&ua.x));
    float2 a1 = __half22float2(*reinterpret_cast<__half2*>(&ua.y));
    float2 b0 = __half22float2(*reinterpret_cast<__half2*>(&ub.x));
    float2 b1 = __half22float2(*reinterpret_cast<__half2*>(&ub.y));
    float2 c0f = __half22float2(*reinterpret_cast<__half2*>(&uc.x));
    float2 c1f = __half22float2(*reinterpret_cast<__half2*>(&uc.y));
    float4 r;
    r.x = __fmul_rn(__fmul_rn(a0.x, b0.x), c0f.x);
    r.y = __fmul_rn(__fmul_rn(a0.y, b0.y), c0f.y);
    r.z = __fmul_rn(__fmul_rn(a1.x, b1.x), c1f.x);
    r.w = __fmul_rn(__fmul_rn(a1.y, b1.y), c1f.y);
    return r;
}

__device__ __forceinline__ float4 gather_prod_f(float t, float px, float py, float pz, int sub) {
    unsigned c0, c1, c2;
    gather_addrs(t, px, py, pz, sub, c0, c1, c2);
    const uint2* base = reinterpret_cast<const uint2*>(g_T16);
    return prod3(__ldg(base + c0), __ldg(base + c1), __ldg(base + c2));
}

__device__ __forceinline__ uint32_t smem_u32(const void* p) {
    uint32_t a;
    asm("{ .reg .u64 t; cvta.to.shared.u64 t, %1; cvt.u32.u64 %0, t; }" : "=r"(a) : "l"(p));
    return a;
}

// Bulk-async store smem -> gmem with evict_first L2 policy (output must not
// evict the L2-resident plane scratch).
__device__ __forceinline__ void bulk_store_ef(void* g, uint32_t s, int bytes) {
    asm volatile(
        "{\n\t"
        ".reg .b64 pol;\n\t"
        "createpolicy.fractional.L2::evict_first.b64 pol, 1.0;\n\t"
        "cp.async.bulk.global.shared::cta.bulk_group.L2::cache_hint [%0], [%1], %2, pol;\n\t"
        "}"
        :: "l"(g), "r"(s), "r"(bytes) : "memory");
}

// ---------------------------------------------------------------------------
// Kernel 2: gather + product. Block = 256 threads = 64 points, 2 pts/thread
// (MLP 6). Results staged in smem, written out via 2 bulk-async (TMA) stores
// per block — removes the 12-cyc STG.128 issue cost that bound the LSU.
// ---------------------------------------------------------------------------
__global__ void __launch_bounds__(256)
displacement_kernel(const float* __restrict__ pts,
                    const float* __restrict__ tim,
                    float* __restrict__ out) {
    __shared__ float  s_p[192];
    __shared__ float  s_t[64];
    __shared__ __align__(16) float4 sA[512];   // 64 pts x 8 chunks, region A (8KB)
    __shared__ __align__(16) float4 sB[512];   // region B (8KB)

    int tid  = threadIdx.x;
    int base = blockIdx.x * 64;

    if (tid < 192)  s_p[tid]       = pts[base * 3 + tid];
    else            s_t[tid - 192] = tim[base + (tid - 192)];
    __syncthreads();

    int il  = tid >> 3;      // local point 0..31 (pair partner: il+32)
    int sub = tid & 7;
    int jl  = il + 32;
    int i1  = base + jl;     // only i1 can be NPTS-1

    float t0  = __fadd_rn(__fmul_rn(s_t[il], 2.0f), -1.0f);
    float px0 = __fmul_rn(-s_p[3 * il + 0], INV_BOUNDS);
    float py0 = __fmul_rn(-s_p[3 * il + 1], INV_BOUNDS);
    float pz0 = __fmul_rn(-s_p[3 * il + 2], INV_BOUNDS);
    float t1  = __fadd_rn(__fmul_rn(s_t[jl], 2.0f), -1.0f);
    float px1 = __fmul_rn(-s_p[3 * jl + 0], INV_BOUNDS);
    float py1 = __fmul_rn(-s_p[3 * jl + 1], INV_BOUNDS);
    float pz1 = __fmul_rn(-s_p[3 * jl + 2], INV_BOUNDS);

    unsigned a0, a1, a2, b0, b1, b2;
    gather_addrs(t0, px0, py0, pz0, sub, a0, a1, a2);
    gather_addrs(t1, px1, py1, pz1, sub, b0, b1, b2);
    const uint2* gbase = reinterpret_cast<const uint2*>(g_T16);
    uint2 va0 = __ldg(gbase + a0);
    uint2 va1 = __ldg(gbase + a1);
    uint2 va2 = __ldg(gbase + a2);
    uint2 vb0 = __ldg(gbase + b0);
    uint2 vb1 = __ldg(gbase + b1);
    uint2 vb2 = __ldg(gbase + b2);

    float4 r0 = prod3(va0, va1, va2);
    float4 r1 = prod3(vb0, vb1, vb2);
    float4 r1A = r1, r1B = r1;

    if (i1 == NPTS - 1) {
        // data_shift subtracts TSTEP from ALL 4 components of the last row only
        float4 r2 = gather_prod_f(__fadd_rn(t1, -TSTEP), __fadd_rn(px1, -TSTEP),
                                  __fadd_rn(py1, -TSTEP), __fadd_rn(pz1, -TSTEP), sub);
        bool cond = __fadd_rn(px1, TSTEP) > 1.0f;   // data[-1,0] + TIME_STEP > 1.0
        r1A = cond ? r2 : r1;
        r1B = cond ? r1 : r2;
    }

    // Stage results: slot = local_point*8 + sub -> tid and tid+256 (linear,
    // conflict-free STS.128).
    sA[tid]       = r0;
    sA[tid + 256] = r1A;
    sB[tid]       = r0;
    sB[tid + 256] = r1B;
    __syncthreads();

    if (tid == 0) {
        asm volatile("fence.proxy.async;" ::: "memory");
        float* gA = out + (size_t)base * FEAT;
        float* gB = out + (size_t)NPTS * FEAT + (size_t)base * FEAT;
        bulk_store_ef(gA, smem_u32(sA), 64 * FEAT * 4);
        bulk_store_ef(gB, smem_u32(sB), 64 * FEAT * 4);
        asm volatile("cp.async.bulk.commit_group;" ::: "memory");
        asm volatile("cp.async.bulk.wait_group 0;" ::: "memory");
    }
}

extern "C" void kernel_launch(void* const* d_in, const int* in_sizes, int n_in,
                              void* d_out, int out_size) {
    const float* pts  = (const float*)d_in[0];
    const float* tim  = (const float*)d_in[1];
    const float* p0   = (const float*)d_in[2];
    const float* p1   = (const float*)d_in[3];
    const float* p2   = (const float*)d_in[4];
    float* out = (float*)d_out;

    // 1) transpose+convert planes to [H,W,F] fp16 (1 block per plane-row)
    transpose_planes<<<3 * RES_H, 256>>>(p0, p1, p2);

    // 2) main gather/product kernel: 64 points per 256-thread block
    displacement_kernel<<<NPTS / 64, 256>>>(pts, tim, out);
}

// round 13
// speedup vs baseline: 1.0798x; 1.0798x over previous
#include <cuda_runtime.h>
#include <cuda_bf16.h>
#include <cuda_fp16.h>
#include <cstdint>

// Problem constants
#define NPTS   1000000
#define FEAT   32
#define RES_H  512
#define RES_W  128
#define TSTEP  (1.0f/256.0f)   // 1/(2*RES_W), exactly representable
// XLA rewrites (-pts / 1.6f) as (-pts * (1/1.6f)); 1/1.6f rounds to exactly 0.625f.
#define INV_BOUNDS 0.625f

// Transposed fp16 planes: [plane][h][w][f] — 3*512*128*32*2 = 12.6 MB, L2-resident.
__device__ __half g_T16[3 * RES_H * RES_W * FEAT];

// ---------------------------------------------------------------------------
// Kernel 1: transpose+convert each plane [F,H,W] fp32 -> [H,W,F] fp16.
// One block per (plane, h): 1536 blocks x 256 threads. Fires the PDL trigger
// as soon as its global writes are issued.
// ---------------------------------------------------------------------------
__global__ void __launch_bounds__(256)
transpose_planes(const float* __restrict__ p0,
                 const float* __restrict__ p1,
                 const float* __restrict__ p2) {
    __shared__ float tile[32][129];
    int b   = blockIdx.x;
    int h   = b & 511;
    int pl  = b >> 9;
    const float* src = (pl == 0) ? p0 : ((pl == 1) ? p1 : p2);
    int tid = threadIdx.x;

    #pragma unroll
    for (int k = 0; k < 16; k++) {
        int idx = tid + 256 * k;
        int f = idx >> 7;
        int w = idx & 127;
        tile[f][w] = src[f * (RES_H * RES_W) + h * RES_W + w];
    }
    __syncthreads();

    __half2* dst = reinterpret_cast<__half2*>(g_T16) + (size_t)(pl * RES_H + h) * (RES_W * FEAT / 2);
    #pragma unroll
    for (int k = 0; k < 8; k++) {
        int idx2 = tid + 256 * k;
        int w  = idx2 >> 4;
        int fp = idx2 & 15;
        dst[idx2] = __floats2half2_rn(tile[2 * fp][w], tile[2 * fp + 1][w]);
    }
    // Allow the dependent (main) kernel to start launching.
    cudaTriggerProgrammaticLaunchCompletion();
}

// ---------------------------------------------------------------------------
// Index math: IEEE round-to-nearest ops, round-half-even conversion.
// ---------------------------------------------------------------------------
__device__ __forceinline__ int idx_w(float c) {
    float v = __fmul_rn(__fmul_rn(__fadd_rn(c, 1.0f), 0.5f), 127.0f);
    int k = __float2int_rn(v);
    return min(127, max(0, k));
}
__device__ __forceinline__ int idx_h(float c) {
    float v = __fmul_rn(__fmul_rn(__fadd_rn(c, 1.0f), 0.5f), 511.0f);
    int k = __float2int_rn(v);
    return min(511, max(0, k));
}

__device__ __forceinline__ void gather_addrs(float t, float px, float py, float pz,
                                             int sub, unsigned& c0, unsigned& c1, unsigned& c2) {
    int ix  = idx_w(t);
    c0 = (unsigned)(((0 * RES_H + idx_h(px)) * RES_W + ix) * (FEAT / 4)) + sub;
    c1 = (unsigned)(((1 * RES_H + idx_h(py)) * RES_W + ix) * (FEAT / 4)) + sub;
    c2 = (unsigned)(((2 * RES_H + idx_h(pz)) * RES_W + ix) * (FEAT / 4)) + sub;
}

__device__ __forceinline__ float4 prod3(uint2 ua, uint2 ub, uint2 uc) {
    float2 a0 = __half22float2(*reinterpret_cast<__half2*>(&ua.x));
    float2 a1 = __half22float2(*reinterpret_cast<__half2*>(&ua.y));
    float2 b0 = __half22float2(*reinterpret_cast<__half2*>(&ub.x));
    float2 b1 = __half22float2(*reinterpret_cast<__half2*>(&ub.y));
    float2 c0f = __half22float2(*reinterpret_cast<__half2*>(&uc.x));
    float2 c1f = __half22float2(*reinterpret_cast<__half2*>(&uc.y));
    float4 r;
    r.x = __fmul_rn(__fmul_rn(a0.x, b0.x), c0f.x);
    r.y = __fmul_rn(__fmul_rn(a0.y, b0.y), c0f.y);
    r.z = __fmul_rn(__fmul_rn(a1.x, b1.x), c1f.x);
    r.w = __fmul_rn(__fmul_rn(a1.y, b1.y), c1f.y);
    return r;
}

__device__ __forceinline__ float4 gather_prod_f(float t, float px, float py, float pz, int sub) {
    unsigned c0, c1, c2;
    gather_addrs(t, px, py, pz, sub, c0, c1, c2);
    const uint2* base = reinterpret_cast<const uint2*>(g_T16);
    return prod3(__ldg(base + c0), __ldg(base + c1), __ldg(base + c2));
}

// ---------------------------------------------------------------------------
// Kernel 2: gather + product + dual write. Block = 256 threads = 64 points,
// 2 pts/thread (MLP 6). Input staging + all index math happen BEFORE the
// grid-dependency sync so they overlap the transpose via PDL.
// ---------------------------------------------------------------------------
__global__ void __launch_bounds__(256)
displacement_kernel(const float* __restrict__ pts,
                    const float* __restrict__ tim,
                    float* __restrict__ out) {
    __shared__ float s_p[192];  // pts for 64 points
    __shared__ float s_t[64];   // tim for 64 points

    int tid  = threadIdx.x;
    int base = blockIdx.x * 64;

    if (tid < 192)  s_p[tid]       = pts[base * 3 + tid];
    else            s_t[tid - 192] = tim[base + (tid - 192)];
    __syncthreads();

    int il  = tid >> 3;      // local point 0..31 (pair partner: il+32)
    int sub = tid & 7;
    int jl  = il + 32;
    int i0  = base + il;
    int i1  = base + jl;     // only i1 can be NPTS-1

    float t0  = __fadd_rn(__fmul_rn(s_t[il], 2.0f), -1.0f);
    float px0 = __fmul_rn(-s_p[3 * il + 0], INV_BOUNDS);
    float py0 = __fmul_rn(-s_p[3 * il + 1], INV_BOUNDS);
    float pz0 = __fmul_rn(-s_p[3 * il + 2], INV_BOUNDS);
    float t1  = __fadd_rn(__fmul_rn(s_t[jl], 2.0f), -1.0f);
    float px1 = __fmul_rn(-s_p[3 * jl + 0], INV_BOUNDS);
    float py1 = __fmul_rn(-s_p[3 * jl + 1], INV_BOUNDS);
    float pz1 = __fmul_rn(-s_p[3 * jl + 2], INV_BOUNDS);

    unsigned a0, a1, a2, b0, b1, b2;
    gather_addrs(t0, px0, py0, pz0, sub, a0, a1, a2);
    gather_addrs(t1, px1, py1, pz1, sub, b0, b1, b2);

    // Wait for the transpose's global writes to be visible, then gather.
    cudaGridDependencySynchronize();

    const uint2* gbase = reinterpret_cast<const uint2*>(g_T16);
    uint2 va0 = __ldg(gbase + a0);
    uint2 va1 = __ldg(gbase + a1);
    uint2 va2 = __ldg(gbase + a2);
    uint2 vb0 = __ldg(gbase + b0);
    uint2 vb1 = __ldg(gbase + b1);
    uint2 vb2 = __ldg(gbase + b2);

    float4 r0 = prod3(va0, va1, va2);
    float4 r1 = prod3(vb0, vb1, vb2);
    float4 r1A = r1, r1B = r1;

    if (i1 == NPTS - 1) {
        // data_shift subtracts TSTEP from ALL 4 components of the last row only
        float4 r2 = gather_prod_f(__fadd_rn(t1, -TSTEP), __fadd_rn(px1, -TSTEP),
                                  __fadd_rn(py1, -TSTEP), __fadd_rn(pz1, -TSTEP), sub);
        bool cond = __fadd_rn(px1, TSTEP) > 1.0f;   // data[-1,0] + TIME_STEP > 1.0
        r1A = cond ? r2 : r1;
        r1B = cond ? r1 : r2;
    }

    // feature_A at [0, N*F), feature_B at [N*F, 2*N*F). Streaming stores keep
    // the 256MB output from evicting the 12.6MB plane scratch in L2.
    float4* o = reinterpret_cast<float4*>(out);
    size_t row0 = (size_t)i0 * 8 + sub;
    size_t row1 = (size_t)i1 * 8 + sub;
    __stcs(o + row0, r0);
    __stcs(o + row1, r1A);
    __stcs(o + (size_t)NPTS * 8 + row0, r0);
    __stcs(o + (size_t)NPTS * 8 + row1, r1B);
}

extern "C" void kernel_launch(void* const* d_in, const int* in_sizes, int n_in,
                              void* d_out, int out_size) {
    const float* pts  = (const float*)d_in[0];
    const float* tim  = (const float*)d_in[1];
    const float* p0   = (const float*)d_in[2];
    const float* p1   = (const float*)d_in[3];
    const float* p2   = (const float*)d_in[4];
    float* out = (float*)d_out;

    // 1) transpose+convert planes to [H,W,F] fp16 (1 block per plane-row)
    transpose_planes<<<3 * RES_H, 256>>>(p0, p1, p2);

    // 2) main kernel launched with PDL so its launch+preamble overlap the
    //    transpose tail; it grid-syncs before touching g_T16.
    cudaLaunchAttribute attrs[1];
    attrs[0].id = cudaLaunchAttributeProgrammaticStreamSerialization;
    attrs[0].val.programmaticStreamSerializationAllowed = 1;

    cudaLaunchConfig_t cfg = {};
    cfg.gridDim  = dim3(NPTS / 64);
    cfg.blockDim = dim3(256);
    cfg.dynamicSmemBytes = 0;
    cfg.stream = 0;
    cfg.attrs = attrs;
    cfg.numAttrs = 1;
    cudaLaunchKernelEx(&cfg, displacement_kernel, pts, tim, out);
}